// round 2
// baseline (speedup 1.0000x reference)
#include <cuda_runtime.h>
#include <cuda_bf16.h>
#include <math.h>

// ---------------------------------------------------------------------------
// 2-layer GCN:  h1 = relu(Agg(x@W1)+b1);  out = log_softmax(Agg(h1@W2)+b2)
// Agg uses symmetric norm with self-loops: out[i] = sum_{e:(s->i)} dinv[s]*dinv[i]*h[s]
//                                                   + dinv[i]^2 * h[i]
// NOTE: edge_index arrives as int32 (JAX x64 disabled demotes int64).
// ---------------------------------------------------------------------------

#define F_IN 512
#define HID  16
#define NCLS 2
#define NMAX 131072

__device__ __align__(16) int   g_degcnt[NMAX];
__device__ __align__(16) float g_dinv[NMAX];
__device__ __align__(16) float g_h1[NMAX * HID];
__device__ __align__(16) float g_acc1[NMAX * HID];
__device__ __align__(16) float g_h2[NMAX * NCLS];
__device__ __align__(16) float g_acc2[NMAX * NCLS];

// ---------------- vector reductions (sm_90+) ----------------
__device__ __forceinline__ void red_add_v4(float* p, float a, float b, float c, float d) {
    asm volatile("red.global.add.v4.f32 [%0], {%1,%2,%3,%4};"
                 :: "l"(p), "f"(a), "f"(b), "f"(c), "f"(d) : "memory");
}
__device__ __forceinline__ void red_add_v2(float* p, float a, float b) {
    asm volatile("red.global.add.v2.f32 [%0], {%1,%2};"
                 :: "l"(p), "f"(a), "f"(b) : "memory");
}

__device__ __forceinline__ float f4c(const float4& v, int i) {
    switch (i) { case 0: return v.x; case 1: return v.y; case 2: return v.z; default: return v.w; }
}

// ---------------- zero scratch ----------------
__global__ void k_zero(int N) {
    int i = blockIdx.x * blockDim.x + threadIdx.x;
    int n16 = N * HID;
    if (i < n16) g_acc1[i] = 0.0f;
    if (i < N) g_degcnt[i] = 0;
    if (i < N * NCLS) g_acc2[i] = 0.0f;
}

// ---------------- degree count ----------------
__global__ void k_deg(const int* __restrict__ dst, int E) {
    int e = blockIdx.x * blockDim.x + threadIdx.x;
    if (e >= E) return;
    atomicAdd(&g_degcnt[dst[e]], 1);
}

__global__ void k_dinv(int N) {
    int i = blockIdx.x * blockDim.x + threadIdx.x;
    if (i >= N) return;
    g_dinv[i] = rsqrtf((float)(g_degcnt[i] + 1));   // +1 self loop; deg>0 always
}

// ---------------- GEMM1: h1 = x @ W1   (N x 512 @ 512 x 16) ----------------
// Block: 128 threads, 128 rows. Thread computes 4 rows x 4 cols micro-tile.
// x staged in smem (padded stride 36 floats); W1 read as float4 from L1.
#define ROWS_BLK 128
#define KC 32
#define XSTR 36

__global__ __launch_bounds__(128) void k_gemm1(const float* __restrict__ x,
                                               const float* __restrict__ W1, int N) {
    __shared__ float xs[ROWS_BLK * XSTR];
    const int tid = threadIdx.x;
    const int row0 = blockIdx.x * ROWS_BLK;
    const int c4 = (tid & 3) * 4;     // column group: 0,4,8,12
    const int rq = tid >> 2;          // row quad: 0..31

    float acc[4][4];
#pragma unroll
    for (int i = 0; i < 4; i++)
#pragma unroll
        for (int j = 0; j < 4; j++) acc[i][j] = 0.0f;

    for (int kc = 0; kc < F_IN; kc += KC) {
        __syncthreads();
        // stage x tile: 128 rows x 32 floats = 1024 float4, coalesced
#pragma unroll
        for (int it = 0; it < 8; it++) {
            int idx = tid + 128 * it;     // 0..1023
            int r = idx >> 3;
            int cq = idx & 7;
            float4 v = make_float4(0.f, 0.f, 0.f, 0.f);
            if (row0 + r < N)
                v = *(const float4*)(x + (size_t)(row0 + r) * F_IN + kc + cq * 4);
            *(float4*)(xs + r * XSTR + cq * 4) = v;
        }
        __syncthreads();

#pragma unroll
        for (int k4 = 0; k4 < KC / 4; k4++) {
            float4 xv[4];
#pragma unroll
            for (int i = 0; i < 4; i++)
                xv[i] = *(const float4*)(xs + (rq * 4 + i) * XSTR + k4 * 4);
#pragma unroll
            for (int kk = 0; kk < 4; kk++) {
                int k = kc + k4 * 4 + kk;
                float4 wv = __ldg((const float4*)(W1 + k * HID + c4));
#pragma unroll
                for (int i = 0; i < 4; i++) {
                    float xk = f4c(xv[i], kk);
                    acc[i][0] = fmaf(xk, wv.x, acc[i][0]);
                    acc[i][1] = fmaf(xk, wv.y, acc[i][1]);
                    acc[i][2] = fmaf(xk, wv.z, acc[i][2]);
                    acc[i][3] = fmaf(xk, wv.w, acc[i][3]);
                }
            }
        }
    }

#pragma unroll
    for (int i = 0; i < 4; i++) {
        int r = row0 + rq * 4 + i;
        if (r < N)
            *(float4*)(g_h1 + (size_t)r * HID + c4) =
                make_float4(acc[i][0], acc[i][1], acc[i][2], acc[i][3]);
    }
}

// ---------------- scatter layer 1 (4 threads per edge) ----------------
__global__ void k_scatter1(const int* __restrict__ src,
                           const int* __restrict__ dst, int E) {
    int t = blockIdx.x * blockDim.x + threadIdx.x;
    if (t >= E * 4) return;
    int e = t >> 2, p = t & 3;
    int s = src[e];
    int d = dst[e];
    float nrm = g_dinv[s] * g_dinv[d];
    float4 h = *(const float4*)(g_h1 + (size_t)s * HID + p * 4);
    red_add_v4(g_acc1 + (size_t)d * HID + p * 4,
               h.x * nrm, h.y * nrm, h.z * nrm, h.w * nrm);
}

// ---------------- per-node: finish layer1 (self loop + bias + relu), h2 = t @ W2 ----
__global__ void k_node1(const float* __restrict__ b1, const float* __restrict__ W2, int N) {
    int i = blockIdx.x * blockDim.x + threadIdx.x;
    if (i >= N) return;
    float di = g_dinv[i];
    float d2 = di * di;
    float o0 = 0.f, o1 = 0.f;
#pragma unroll
    for (int q = 0; q < 4; q++) {
        float4 a = *(const float4*)(g_acc1 + (size_t)i * HID + q * 4);
        float4 h = *(const float4*)(g_h1 + (size_t)i * HID + q * 4);
        float4 bb = __ldg((const float4*)(b1 + q * 4));
        float t0 = fmaxf(a.x + d2 * h.x + bb.x, 0.f);
        float t1 = fmaxf(a.y + d2 * h.y + bb.y, 0.f);
        float t2 = fmaxf(a.z + d2 * h.z + bb.z, 0.f);
        float t3 = fmaxf(a.w + d2 * h.w + bb.w, 0.f);
        int c = q * 4;
        o0 = fmaf(t0, __ldg(W2 + (c + 0) * NCLS + 0), o0);
        o1 = fmaf(t0, __ldg(W2 + (c + 0) * NCLS + 1), o1);
        o0 = fmaf(t1, __ldg(W2 + (c + 1) * NCLS + 0), o0);
        o1 = fmaf(t1, __ldg(W2 + (c + 1) * NCLS + 1), o1);
        o0 = fmaf(t2, __ldg(W2 + (c + 2) * NCLS + 0), o0);
        o1 = fmaf(t2, __ldg(W2 + (c + 2) * NCLS + 1), o1);
        o0 = fmaf(t3, __ldg(W2 + (c + 3) * NCLS + 0), o0);
        o1 = fmaf(t3, __ldg(W2 + (c + 3) * NCLS + 1), o1);
    }
    g_h2[i * NCLS + 0] = o0;
    g_h2[i * NCLS + 1] = o1;
}

// ---------------- scatter layer 2 (1 thread per edge) ----------------
__global__ void k_scatter2(const int* __restrict__ src,
                           const int* __restrict__ dst, int E) {
    int e = blockIdx.x * blockDim.x + threadIdx.x;
    if (e >= E) return;
    int s = src[e];
    int d = dst[e];
    float nrm = g_dinv[s] * g_dinv[d];
    float h0 = g_h2[s * NCLS + 0];
    float h1v = g_h2[s * NCLS + 1];
    red_add_v2(g_acc2 + (size_t)d * NCLS, h0 * nrm, h1v * nrm);
}

// ---------------- final: self loop + bias + log_softmax ----------------
__global__ void k_out(const float* __restrict__ b2, float* __restrict__ out, int N) {
    int i = blockIdx.x * blockDim.x + threadIdx.x;
    if (i >= N) return;
    float di = g_dinv[i];
    float d2 = di * di;
    float v0 = g_acc2[i * NCLS + 0] + d2 * g_h2[i * NCLS + 0] + __ldg(b2 + 0);
    float v1 = g_acc2[i * NCLS + 1] + d2 * g_h2[i * NCLS + 1] + __ldg(b2 + 1);
    float m = fmaxf(v0, v1);
    float lse = m + logf(expf(v0 - m) + expf(v1 - m));
    out[i * NCLS + 0] = v0 - lse;
    out[i * NCLS + 1] = v1 - lse;
}

// ---------------------------------------------------------------------------
extern "C" void kernel_launch(void* const* d_in, const int* in_sizes, int n_in,
                              void* d_out, int out_size) {
    const float* x = (const float*)d_in[0];
    const int* ei = (const int*)d_in[1];
    const float* W1 = (const float*)d_in[2];
    const float* b1 = (const float*)d_in[3];
    const float* W2 = (const float*)d_in[4];
    const float* b2 = (const float*)d_in[5];
    float* out = (float*)d_out;

    const int N = in_sizes[0] / F_IN;
    const int E = in_sizes[1] / 2;
    const int* src = ei;
    const int* dst = ei + E;

    k_zero<<<(N * HID + 255) / 256, 256>>>(N);
    k_deg<<<(E + 255) / 256, 256>>>(dst, E);
    k_dinv<<<(N + 255) / 256, 256>>>(N);
    k_gemm1<<<(N + ROWS_BLK - 1) / ROWS_BLK, 128>>>(x, W1, N);
    k_scatter1<<<(E * 4 + 255) / 256, 256>>>(src, dst, E);
    k_node1<<<(N + 255) / 256, 256>>>(b1, W2, N);
    k_scatter2<<<(E + 255) / 256, 256>>>(src, dst, E);
    k_out<<<(N + 255) / 256, 256>>>(b2, out, N);
}